// round 13
// baseline (speedup 1.0000x reference)
#include <cuda_runtime.h>
#include <cuda_fp16.h>
#include <math.h>
#include <stdint.h>

// ---------------------------------------------------------------------------
// Problem constants
// ---------------------------------------------------------------------------
#define BATCH 4096
#define SEQ   41
#define FDIM  128
#define SF    (SEQ*FDIM)        // 5248
#define C64L  (64*128)          // 8192

// ---------------------------------------------------------------------------
// Scratch (device globals; allocation-free contract)
// ---------------------------------------------------------------------------
__device__ __align__(256) __half g_h0[(size_t)BATCH * SF];   // activation ping
__device__ __align__(256) __half g_h1[(size_t)BATCH * SF];   // activation pong
__device__ __align__(256) __half g_c[(size_t)BATCH * C64L];  // conv1 out [b][l=128][o=64]
__device__ __align__(256) float  g_g1[(size_t)BATCH * 128];  // [B,2,64]
__device__ __align__(256) float  g_g2[(size_t)BATCH * 64];   // [B,2,32]
__device__ double g_bnsum[64], g_bnsq[64];
__device__ double g_bn1acc[4];
__device__ double g_bn2acc[4];

// transposed fp16 PL weights: layout [s][n=128][K], layers packed
#define WOFF3 ((size_t)0)
#define WOFF5 ((size_t)41*384*128)
#define WOFF7 ((size_t)(41*384*128) + (size_t)41*640*128)
#define WTOT  ((size_t)41*1920*128)
__device__ __align__(256) __half g_w16[WTOT];

// conv weights fp16, pitched: wc1 [3][64][56], wc2 [3][64][40]
__device__ __align__(256) __half g_wc1[3*64*56];
__device__ __align__(256) __half g_wc2[3*64*40];

// single shared extern symbol for all dynamic-smem kernels
extern __shared__ __align__(1024) char sm_raw[];

__device__ __forceinline__ float squash_factor(float ssq) {
    float n = sqrtf(ssq);
    return (1.f - 1.f / (expf(n) + 1e-21f)) / (n + 1e-21f);
}

// ---------------------------------------------------------------------------
// PTX helpers (compute_100-safe: mma.sync + cp.async + ldmatrix)
// ---------------------------------------------------------------------------
__device__ __forceinline__ uint32_t smem_u32(const void* p) {
    uint32_t a;
    asm("{ .reg .u64 t; cvta.to.shared.u64 t, %1; cvt.u32.u64 %0, t; }" : "=r"(a) : "l"(p));
    return a;
}
__device__ __forceinline__ uint32_t lds32(uint32_t a) {
    uint32_t v;
    asm volatile("ld.shared.b32 %0, [%1];" : "=r"(v) : "r"(a));
    return v;
}
__device__ __forceinline__ void sts32(uint32_t a, uint32_t v) {
    asm volatile("st.shared.b32 [%0], %1;" :: "r"(a), "r"(v));
}
__device__ __forceinline__ void sts16(uint32_t a, uint16_t v) {
    asm volatile("st.shared.u16 [%0], %1;" :: "r"(a), "h"(v));
}
__device__ __forceinline__ void ldsm_x4(uint32_t* r, uint32_t addr) {
    asm volatile("ldmatrix.sync.aligned.m8n8.x4.shared.b16 {%0,%1,%2,%3}, [%4];"
        : "=r"(r[0]), "=r"(r[1]), "=r"(r[2]), "=r"(r[3]) : "r"(addr));
}
__device__ __forceinline__ void mma_f16(float* c, const uint32_t* a, const uint32_t* b) {
    asm volatile(
        "mma.sync.aligned.m16n8k16.row.col.f32.f16.f16.f32 "
        "{%0,%1,%2,%3}, {%4,%5,%6,%7}, {%8,%9}, {%0,%1,%2,%3};"
        : "+f"(c[0]), "+f"(c[1]), "+f"(c[2]), "+f"(c[3])
        : "r"(a[0]), "r"(a[1]), "r"(a[2]), "r"(a[3]), "r"(b[0]), "r"(b[1]));
}
#define CP16(dst, src)    asm volatile("cp.async.cg.shared.global [%0], [%1], 16;" :: "r"(dst), "l"(src))
#define CP_COMMIT()       asm volatile("cp.async.commit_group;" ::: "memory")
#define CP_WAIT0()        asm volatile("cp.async.wait_group 0;" ::: "memory")

__device__ __forceinline__ uint32_t hpack(float a, float b) {
    __half2 t = __floats2half2_rn(a, b);
    return *reinterpret_cast<uint32_t*>(&t);
}

// ---------------------------------------------------------------------------
// 0. prep_misc: conv weight prep + accumulator zero + embedding gather
// ---------------------------------------------------------------------------
__global__ void prep_misc(const float* __restrict__ c1w, const float* __restrict__ c2w,
                          const int* __restrict__ x, const float* __restrict__ emb) {
    int bx = blockIdx.x;
    if (bx < 42) {
        int t = bx * 256 + threadIdx.x;
        if (bx == 0) {
            int tt = threadIdx.x;
            if (tt < 64) { g_bnsum[tt] = 0.0; g_bnsq[tt] = 0.0; }
            if (tt < 4)  { g_bn1acc[tt] = 0.0; g_bn2acc[tt] = 0.0; }
        }
        if (t < 3 * 64 * 56) {
            int c = t % 56, o = (t / 56) % 64, k = t / (56 * 64);
            g_wc1[t] = (c < 41) ? __float2half(c1w[(o * 41 + c) * 3 + k]) : __float2half(0.f);
        }
        if (t < 3 * 64 * 40) {
            int c = t % 40, o = (t / 40) % 64, k = t / (40 * 64);
            g_wc2[t] = (c < 32) ? __float2half(c2w[(o * 32 + c) * 3 + k]) : __float2half(0.f);
        }
    } else {
        int gid = (bx - 42) * 256 + threadIdx.x;
        int pos = gid >> 4;
        int f0  = (gid & 15) * 8;
        if (pos >= BATCH * SEQ) return;
        int e = x[pos];
        const float4* sp = reinterpret_cast<const float4*>(emb + e * FDIM + f0);
        float4 v0 = sp[0], v1 = sp[1];
        uint4 o;
        o.x = hpack(v0.x, v0.y); o.y = hpack(v0.z, v0.w);
        o.z = hpack(v1.x, v1.y); o.w = hpack(v1.z, v1.w);
        *reinterpret_cast<uint4*>(g_h0 + (size_t)pos * FDIM + f0) = o;
    }
}

// ---------------------------------------------------------------------------
// 1b. PL weight prep, all 3 layers in one launch.
// ---------------------------------------------------------------------------
__global__ void wprep_all(const float* __restrict__ W3, const float* __restrict__ W5,
                          const float* __restrict__ W7) {
    __shared__ float tile[32][129];
    int bx = blockIdx.x, s = blockIdx.y, t = threadIdx.x;
    const float* W; __half* o; int K, kb;
    if (bx < 12)      { W = W3; o = g_w16 + WOFF3; K = 384; kb = bx * 32; }
    else if (bx < 32) { W = W5; o = g_w16 + WOFF5; K = 640; kb = (bx - 12) * 32; }
    else              { W = W7; o = g_w16 + WOFF7; K = 896; kb = (bx - 32) * 32; }
#pragma unroll
    for (int i = 0; i < 16; i++) {
        int e = t + i * 256;
        int kk = e >> 7, n = e & 127;
        tile[kk][n] = W[((size_t)s * K + kb + kk) * 128 + n];
    }
    __syncthreads();
    int n = t >> 1, h = (t & 1) * 16;
    size_t ob = ((size_t)(s * 128 + n)) * K + kb + h;
#pragma unroll
    for (int kk = 0; kk < 16; kk += 2) {
        *reinterpret_cast<uint32_t*>(&o[ob + kk]) = hpack(tile[h + kk][n], tile[h + kk + 1][n]);
    }
}

// ---------------------------------------------------------------------------
// 2-4. position_linear: fp16 MMA, 512 threads, 16 warps 4(M)x4(N),
//      warp tile 32x32, K-chunk 64, ldmatrix, 3-stage pipeline.
// ---------------------------------------------------------------------------
#define PL_SMEM (3 * 32768)   // 98304

template<int WIN>
__global__ void __launch_bounds__(512, 2)
pl_kernel(const __half* __restrict__ aIn, const __half* __restrict__ wIn,
          const float* __restrict__ bst, __half* __restrict__ aOut)
{
    constexpr int P = WIN / 2;
    constexpr int K = WIN * 128;
    const uint32_t smb = smem_u32(sm_raw);
    const int s   = blockIdx.y;
    const int bm  = blockIdx.x * 128;
    const int tid = threadIdx.x;
    const int warp = tid >> 5, lane = tid & 31;
    const int warp_m = warp >> 2, warp_n = warp & 3;
    const int gid = lane >> 2, tg = lane & 3;

    const int j0 = (P - s) > 0 ? (P - s) : 0;
    const int j1 = (WIN - 1) < (P + SEQ - 1 - s) ? (WIN - 1) : (P + SEQ - 1 - s);
    const int nst = (j1 - j0 + 1) * 2;     // k64 stages (>= 4 always)

    const int a_moff = (lane & 7) + ((lane >> 3) & 1) * 8;
    const int a_cbit = lane >> 4;
    const int b_roff = ((lane >> 4) & 1) * 8 + (lane & 7);
    const int b_cbit = (lane >> 3) & 1;

    float acc[2][4][4];
#pragma unroll
    for (int a = 0; a < 2; a++)
#pragma unroll
        for (int b = 0; b < 4; b++)
#pragma unroll
            for (int c = 0; c < 4; c++) acc[a][b][c] = 0.f;

    auto load_stage = [&](int st) {
        const int jj = j0 + (st >> 1);
        const int f0 = (st & 1) * 64;
        const int tsrc = s + jj - P;
        const int k0 = jj * 128 + f0;
        const uint32_t sb = smb + (uint32_t)(st % 3) * 32768;
#pragma unroll
        for (int i = 0; i < 2; i++) {
            int idx = tid + i * 512;           // 0..1023
            int row = idx >> 3, ch = idx & 7;
            uint32_t d = sb + row * 128 + (((ch ^ (row & 7)) << 4));
            size_t aoff = ((size_t)(bm + row) * SEQ + tsrc) * 128 + f0 + ch * 8;
            size_t boff = ((size_t)(s * 128 + row)) * K + k0 + ch * 8;
            CP16(d,         (const char*)(aIn + aoff));
            CP16(d + 16384, (const char*)(wIn + boff));
        }
        CP_COMMIT();
    };

    load_stage(0);
    load_stage(1);

    for (int st = 0; st < nst; st++) {
        if (st + 1 < nst) {
            asm volatile("cp.async.wait_group 1;" ::: "memory");
        } else {
            asm volatile("cp.async.wait_group 0;" ::: "memory");
        }
        __syncthreads();

        if (st + 2 < nst) load_stage(st + 2);

        const uint32_t ab = smb + (uint32_t)(st % 3) * 32768;
#pragma unroll
        for (int kt = 0; kt < 4; kt++) {
            uint32_t bf[4][2];
#pragma unroll
            for (int p = 0; p < 2; p++) {
                int row = warp_n * 32 + p * 16 + b_roff;
                int sw = row & 7;
                uint32_t addr = ab + 16384 + row * 128 + (((kt * 2 + b_cbit) ^ sw) << 4);
                uint32_t r[4];
                ldsm_x4(r, addr);
                bf[2 * p][0] = r[0]; bf[2 * p][1] = r[1];
                bf[2 * p + 1][0] = r[2]; bf[2 * p + 1][1] = r[3];
            }
#pragma unroll
            for (int mt = 0; mt < 2; mt++) {
                int row = warp_m * 32 + mt * 16 + a_moff;
                int sw = row & 7;
                uint32_t addr = ab + row * 128 + (((kt * 2 + a_cbit) ^ sw) << 4);
                uint32_t af[4];
                ldsm_x4(af, addr);
#pragma unroll
                for (int nt = 0; nt < 4; nt++)
                    mma_f16(acc[mt][nt], af, bf[nt]);
            }
        }
    }

    const float* bias = bst + s * 128;
#pragma unroll
    for (int mt = 0; mt < 2; mt++) {
        int rbase = warp_m * 32 + mt * 16 + gid;
#pragma unroll
        for (int half = 0; half < 2; half++) {
            int r = rbase + half * 8;
            size_t ob = ((size_t)(bm + r) * SEQ + s) * 128;
#pragma unroll
            for (int nt = 0; nt < 4; nt++) {
                int col = warp_n * 32 + nt * 8 + tg * 2;
                float v0 = fmaxf(acc[mt][nt][half * 2 + 0] + bias[col],     0.f);
                float v1 = fmaxf(acc[mt][nt][half * 2 + 1] + bias[col + 1], 0.f);
                *reinterpret_cast<uint32_t*>(aOut + ob + col) = hpack(v0, v1);
            }
        }
    }
}

// ---------------------------------------------------------------------------
// 5. conv1 via tensor cores. 2 batches per CTA.
// ---------------------------------------------------------------------------
#define C1_STG   0
#define C1_A     10496
#define C1_W     (C1_A + 130*112)        // 25056
#define C1_STATS (C1_W + 3*64*112)       // 46560
#define CONV1_SMEM (C1_STATS + 2*64*4)   // 47072

__global__ void __launch_bounds__(256, 2)
conv1_kernel(const float* __restrict__ bias) {
    const uint32_t smb = smem_u32(sm_raw);
    const int t = threadIdx.x;
    const int warp = t >> 5, lane = t & 31;
    const int warp_m = warp >> 1, warp_n = warp & 1;
    const int gid = lane >> 2, tg = lane & 3;

    for (int i = t; i < 130 * 112 / 4; i += 256) sts32(smb + C1_A + i * 4, 0u);
    for (int i = t; i < 128; i += 256) sts32(smb + C1_STATS + i * 4, 0u);

    {
        const char* src = (const char*)(g_h1 + (size_t)(blockIdx.x * 2) * SF);
        for (int i = t; i < 41 * 16; i += 256)
            CP16(smb + C1_STG + i * 16, src + i * 16);
        const char* wsrc = (const char*)g_wc1;
        for (int i = t; i < 3 * 64 * 56 * 2 / 16; i += 256)
            CP16(smb + C1_W + i * 16, wsrc + i * 16);
        CP_COMMIT(); CP_WAIT0();
    }
    __syncthreads();

    float s0[4], s1[4], q0[4], q1[4];
#pragma unroll
    for (int nt = 0; nt < 4; nt++) { s0[nt] = s1[nt] = q0[nt] = q1[nt] = 0.f; }

    for (int bb2 = 0; bb2 < 2; bb2++) {
        const int b = blockIdx.x * 2 + bb2;

        for (int idx = t; idx < 41 * 64; idx += 256) {
            int c = idx >> 6, f2 = idx & 63;
            uint32_t v = lds32(smb + C1_STG + c * 256 + f2 * 4);
            sts16(smb + C1_A + (2 * f2 + 1) * 112 + c * 2, (uint16_t)(v & 0xFFFF));
            sts16(smb + C1_A + (2 * f2 + 2) * 112 + c * 2, (uint16_t)(v >> 16));
        }
        __syncthreads();

        if (bb2 == 0) {
            const char* src = (const char*)(g_h1 + (size_t)(b + 1) * SF);
            for (int i = t; i < 41 * 16; i += 256)
                CP16(smb + C1_STG + i * 16, src + i * 16);
            CP_COMMIT();
        }

        float acc[2][4][4];
#pragma unroll
        for (int a = 0; a < 2; a++)
#pragma unroll
            for (int bb = 0; bb < 4; bb++)
#pragma unroll
                for (int c = 0; c < 4; c++) acc[a][bb][c] = 0.f;

#pragma unroll
        for (int k = 0; k < 3; k++) {
#pragma unroll
            for (int ks = 0; ks < 3; ks++) {
                uint32_t bf[4][2];
#pragma unroll
                for (int nt = 0; nt < 4; nt++) {
                    uint32_t ba = smb + C1_W + k * (64 * 112) + (warp_n * 32 + nt * 8 + gid) * 112 + ks * 32 + tg * 4;
                    bf[nt][0] = lds32(ba);
                    bf[nt][1] = lds32(ba + 16);
                }
#pragma unroll
                for (int mt = 0; mt < 2; mt++) {
                    int r0 = warp_m * 32 + mt * 16 + gid + k;
                    uint32_t a0a = smb + C1_A + r0 * 112 + ks * 32 + tg * 4;
                    uint32_t a1a = a0a + 8 * 112;
                    uint32_t af[4];
                    af[0] = lds32(a0a);
                    af[1] = lds32(a1a);
                    af[2] = lds32(a0a + 16);
                    af[3] = lds32(a1a + 16);
#pragma unroll
                    for (int nt = 0; nt < 4; nt++)
                        mma_f16(acc[mt][nt], af, bf[nt]);
                }
            }
        }

        __half* dst = g_c + (size_t)b * C64L;
#pragma unroll
        for (int mt = 0; mt < 2; mt++) {
            int l0 = warp_m * 32 + mt * 16 + gid;
#pragma unroll
            for (int nt = 0; nt < 4; nt++) {
                int o = warp_n * 32 + nt * 8 + tg * 2;
                float bb0 = bias[o], bb1 = bias[o + 1];
                float v0 = acc[mt][nt][0] + bb0, v1 = acc[mt][nt][1] + bb1;
                float v2 = acc[mt][nt][2] + bb0, v3 = acc[mt][nt][3] + bb1;
                *reinterpret_cast<uint32_t*>(dst + l0 * 64 + o)       = hpack(v0, v1);
                *reinterpret_cast<uint32_t*>(dst + (l0 + 8) * 64 + o) = hpack(v2, v3);
                s0[nt] += v0 + v2; s1[nt] += v1 + v3;
                q0[nt] += v0 * v0 + v2 * v2; q1[nt] += v1 * v1 + v3 * v3;
            }
        }

        if (bb2 == 0) { CP_WAIT0(); }
        __syncthreads();
    }

#pragma unroll
    for (int nt = 0; nt < 4; nt++) {
#pragma unroll
        for (int off = 4; off < 32; off <<= 1) {
            s0[nt] += __shfl_xor_sync(0xffffffffu, s0[nt], off);
            s1[nt] += __shfl_xor_sync(0xffffffffu, s1[nt], off);
            q0[nt] += __shfl_xor_sync(0xffffffffu, q0[nt], off);
            q1[nt] += __shfl_xor_sync(0xffffffffu, q1[nt], off);
        }
    }
    if (gid == 0) {
        float* sums = reinterpret_cast<float*>(sm_raw + C1_STATS);
        float* sqs  = sums + 64;
#pragma unroll
        for (int nt = 0; nt < 4; nt++) {
            int o = warp_n * 32 + nt * 8 + tg * 2;
            atomicAdd(&sums[o],     s0[nt]);
            atomicAdd(&sums[o + 1], s1[nt]);
            atomicAdd(&sqs[o],      q0[nt]);
            atomicAdd(&sqs[o + 1],  q1[nt]);
        }
    }
    __syncthreads();
    if (t < 64) {
        float* sums = reinterpret_cast<float*>(sm_raw + C1_STATS);
        atomicAdd(&g_bnsum[t], (double)sums[t]);
        atomicAdd(&g_bnsq[t],  (double)sums[64 + t]);
    }
}

// ---------------------------------------------------------------------------
// 8-9. FUSED capsroute (3 CTAs/SM) — BN params computed locally
// ---------------------------------------------------------------------------
#define CR_A    0
#define CR_W    16640
#define CR_SOUT 32000
#define CR_SMEM (CR_SOUT + 128*73*4)   // 69376

__global__ void __launch_bounds__(256, 3)
capsroute_kernel(const float* __restrict__ bng, const float* __restrict__ bnb,
                 const float* __restrict__ cb,
                 const float* __restrict__ rW, const float* __restrict__ rb,
                 const float* __restrict__ fc1)
{
    const uint32_t smb = smem_u32(sm_raw);
    float* sout = reinterpret_cast<float*>(sm_raw + CR_SOUT);  // [128 l][73]
    __shared__ float bnsc[64], bnsh[64];
    __shared__ float red4[4][64];
    __shared__ float sfac[64];
    __shared__ float coef[2][64];
    __shared__ float warp_sq[8];
    __shared__ float factor_s[2];
    __shared__ float sv_s[2][128];
    __shared__ float yv_s[2][128];

    const int b = blockIdx.x, t = threadIdx.x;
    const int warp = t >> 5, lane = t & 31;
    const int warp_m = warp >> 1, g = warp & 1;
    const int gid = lane >> 2, tg = lane & 3;

    // zero halo rows 0 and 129; local BN params
    if (t < 64) {
        sts32(smb + CR_A + ((t < 32) ? 0 : (129 * 128)) + (t & 31) * 4, 0u);
        double inv = 1.0 / ((double)BATCH * 128.0);
        double mu = g_bnsum[t] * inv;
        double var = g_bnsq[t] * inv - mu * mu;
        float sc = bng[t] * rsqrtf((float)var + 1e-5f);
        bnsc[t] = sc;
        bnsh[t] = bnb[t] - (float)mu * sc;
    }

    {
        const char* src = (const char*)(g_c + (size_t)b * C64L);
        for (int i = t; i < 128 * 8; i += 256) {
            int row = (i >> 3) + 1, ch = i & 7;
            CP16(smb + CR_A + row * 128 + ((ch ^ (row & 7)) << 4), src + (row - 1) * 128 + ch * 16);
        }
        const char* wsrc = (const char*)g_wc2;
        for (int i = t; i < 3 * 64 * 40 * 2 / 16; i += 256)
            CP16(smb + CR_W + i * 16, wsrc + i * 16);
        CP_COMMIT(); CP_WAIT0();
    }
    __syncthreads();

    // BN + ReLU in place on A rows 1..128
    for (int idx = t; idx < 128 * 32; idx += 256) {
        int r = (idx >> 5) + 1, wd = idx & 31;
        int o = wd * 2;
        uint32_t addr = smb + CR_A + r * 128 + (((wd >> 2) ^ (r & 7)) << 4) + ((wd * 4) & 15);
        uint32_t v = lds32(addr);
        __half2 h = *reinterpret_cast<__half2*>(&v);
        float f0 = fmaxf(__low2float(h)  * bnsc[o]     + bnsh[o],     0.f);
        float f1 = fmaxf(__high2float(h) * bnsc[o + 1] + bnsh[o + 1], 0.f);
        sts32(addr, hpack(f0, f1));
    }
    __syncthreads();

    float acc[2][4][4];
#pragma unroll
    for (int a = 0; a < 2; a++)
#pragma unroll
        for (int bb = 0; bb < 4; bb++)
#pragma unroll
            for (int c = 0; c < 4; c++) acc[a][bb][c] = 0.f;

#pragma unroll
    for (int k = 0; k < 3; k++) {
#pragma unroll
        for (int ks = 0; ks < 2; ks++) {
            uint32_t bf[4][2];
#pragma unroll
            for (int nt = 0; nt < 4; nt++) {
                uint32_t ba = smb + CR_W + k * (64 * 80) + (g * 32 + nt * 8 + gid) * 80 + ks * 32 + tg * 4;
                bf[nt][0] = lds32(ba);
                bf[nt][1] = lds32(ba + 16);
            }
            int cbase = g * 4 + ks * 2;
#pragma unroll
            for (int mt = 0; mt < 2; mt++) {
                int r0 = warp_m * 32 + mt * 16 + gid + k;
                int r1 = r0 + 8;
                uint32_t af[4];
                af[0] = lds32(smb + CR_A + r0 * 128 + (((cbase)     ^ (r0 & 7)) << 4) + tg * 4);
                af[1] = lds32(smb + CR_A + r1 * 128 + (((cbase)     ^ (r1 & 7)) << 4) + tg * 4);
                af[2] = lds32(smb + CR_A + r0 * 128 + (((cbase + 1) ^ (r0 & 7)) << 4) + tg * 4);
                af[3] = lds32(smb + CR_A + r1 * 128 + (((cbase + 1) ^ (r1 & 7)) << 4) + tg * 4);
#pragma unroll
                for (int nt = 0; nt < 4; nt++)
                    mma_f16(acc[mt][nt], af, bf[nt]);
            }
        }
    }

#pragma unroll
    for (int mt = 0; mt < 2; mt++) {
        int l0 = warp_m * 32 + mt * 16 + gid;
#pragma unroll
        for (int nt = 0; nt < 4; nt++) {
            int o = g * 32 + nt * 8 + tg * 2;
            float bb0 = cb[o], bb1 = cb[o + 1];
            sout[l0 * 73 + o]           = acc[mt][nt][0] + bb0;
            sout[l0 * 73 + o + 1]       = acc[mt][nt][1] + bb1;
            sout[(l0 + 8) * 73 + o]     = acc[mt][nt][2] + bb0;
            sout[(l0 + 8) * 73 + o + 1] = acc[mt][nt][3] + bb1;
        }
    }
    __syncthreads();

    {
        int o = t & 63, seg = t >> 6;
        float p = 0.f;
        for (int l = seg * 32; l < seg * 32 + 32; l++) {
            float v = sout[l * 73 + o];
            p += v * v;
        }
        red4[seg][o] = p;
    }
    __syncthreads();
    if (t < 64) {
        float tot = red4[0][t] + red4[1][t] + red4[2][t] + red4[3][t];
        sfac[t] = squash_factor(tot);
    }
    __syncthreads();
    if (t < 128) {
        int i = t >> 6, j = t & 63;
        coef[i][j] = sfac[j] * (1.0f + rb[i * 64 + j]);
    }
    __syncthreads();

    int i = t >> 7;
    int f = t & 127;
    float acc2 = 0.f;
    const float* rwi = rW + i * 8192 + f;
    const float* srow = sout + f * 73;
#pragma unroll 8
    for (int j = 0; j < 64; j++)
        acc2 += srow[j] * rwi[j * 128] * coef[i][j];

    float sq = acc2 * acc2;
    for (int off = 16; off; off >>= 1) sq += __shfl_xor_sync(0xffffffffu, sq, off);
    if ((t & 31) == 0) warp_sq[t >> 5] = sq;
    __syncthreads();
    if (t < 2) {
        float tot = warp_sq[t * 4 + 0] + warp_sq[t * 4 + 1] + warp_sq[t * 4 + 2] + warp_sq[t * 4 + 3];
        factor_s[t] = squash_factor(tot);
    }
    __syncthreads();
    sv_s[i][f] = acc2 * factor_s[i];
    __syncthreads();
    yv_s[i][f] = sv_s[i][f] + fmaxf(sv_s[0][f], sv_s[1][f]);
    __syncthreads();

    {
        int ii = t >> 7;
        int o  = (t >> 1) & 63;
        int p  = t & 1;
        float a = 0.f;
        const float* yb = yv_s[ii];
        const float* fb = fc1 + p * 64 * 64 + o;
#pragma unroll 8
        for (int ff = 0; ff < 64; ff++) a += yb[p * 64 + ff] * fb[ff * 64];
        a += __shfl_xor_sync(0xffffffffu, a, 1);
        double s = 0.0, q = 0.0;
        if (p == 0) {
            g_g1[(size_t)b * 128 + ii * 64 + o] = a;
            s = a; q = (double)a * a;
        }
        for (int off = 16; off; off >>= 1) {
            s += __shfl_xor_sync(0xffffffffu, s, off);
            q += __shfl_xor_sync(0xffffffffu, q, off);
        }
        if ((t & 31) == 0) {
            atomicAdd(&g_bn1acc[ii], s);
            atomicAdd(&g_bn1acc[2 + ii], q);
        }
    }
}

// ---------------------------------------------------------------------------
// 11. head1 (bn1 params computed locally)
// ---------------------------------------------------------------------------
__global__ void head1_kernel(const float* __restrict__ bn1g, const float* __restrict__ bn1b,
                             const float* __restrict__ fc2) {
    __shared__ float a_s[4][128];
    __shared__ float p1[4];
    int t = threadIdx.x;
    if (t < 2) {
        double inv = 1.0 / ((double)BATCH * 64.0);
        double mu = g_bn1acc[t] * inv;
        double var = g_bn1acc[2 + t] * inv - mu * mu;
        float sc = bn1g[t] * rsqrtf((float)var + 1e-5f);
        p1[t] = sc;
        p1[2 + t] = bn1b[t] - (float)mu * sc;
    }
    __syncthreads();
    for (int idx = t; idx < 512; idx += 256) {
        int lbb = idx >> 7, rr = idx & 127;
        int ii = rr >> 6;
        float v = g_g1[(size_t)(blockIdx.x * 4 + lbb) * 128 + rr];
        a_s[lbb][rr] = fmaxf(v * p1[ii] + p1[2 + ii], 0.f);
    }
    __syncthreads();
    int lb = t >> 6, r = t & 63;
    int b = blockIdx.x * 4 + lb;
    int ii = r >> 5, m = r & 31;
    float acc = 0.f;
    const float* arow = &a_s[lb][ii * 64];
#pragma unroll 8
    for (int o = 0; o < 64; o++) acc += arow[o] * fc2[o * 32 + m];
    g_g2[(size_t)b * 64 + ii * 32 + m] = acc;
    double s = acc, q = (double)acc * acc;
    for (int off = 16; off; off >>= 1) {
        s += __shfl_xor_sync(0xffffffffu, s, off);
        q += __shfl_xor_sync(0xffffffffu, q, off);
    }
    if ((t & 31) == 0) {
        atomicAdd(&g_bn2acc[ii], s);
        atomicAdd(&g_bn2acc[2 + ii], q);
    }
}

// ---------------------------------------------------------------------------
// 13. head2 (bn2 params computed locally)
// ---------------------------------------------------------------------------
__global__ void head2_kernel(const float* __restrict__ bn2g, const float* __restrict__ bn2b,
                             const float* __restrict__ fc3, float* __restrict__ out) {
    __shared__ float p2[4];
    if (threadIdx.x < 2) {
        int i = threadIdx.x;
        double inv = 1.0 / ((double)BATCH * 32.0);
        double mu = g_bn2acc[i] * inv;
        double var = g_bn2acc[2 + i] * inv - mu * mu;
        float sc = bn2g[i] * rsqrtf((float)var + 1e-5f);
        p2[i] = sc;
        p2[2 + i] = bn2b[i] - (float)mu * sc;
    }
    __syncthreads();
    int b = blockIdx.x * 256 + threadIdx.x;
    if (b >= BATCH) return;
    float best = -1e30f;
#pragma unroll
    for (int i = 0; i < 2; i++) {
        float sc = p2[i], sh = p2[2 + i];
        float s = 0.f;
#pragma unroll
        for (int m = 0; m < 32; m++) {
            float v = fmaxf(g_g2[(size_t)b * 64 + i * 32 + m] * sc + sh, 0.f);
            s += v * fc3[m];
        }
        float sig = 1.f / (1.f + expf(-s));
        best = fmaxf(best, sig);
    }
    out[b] = best;
}

// ---------------------------------------------------------------------------
// launch
// ---------------------------------------------------------------------------
extern "C" void kernel_launch(void* const* d_in, const int* in_sizes, int n_in,
                              void* d_out, int out_size)
{
    const int*   x      = (const int*)d_in[0];
    const float* emb    = (const float*)d_in[1];
    const float* W3     = (const float*)d_in[2];
    const float* b3     = (const float*)d_in[3];
    const float* W5     = (const float*)d_in[4];
    const float* b5     = (const float*)d_in[5];
    const float* W7     = (const float*)d_in[6];
    const float* b7     = (const float*)d_in[7];
    const float* conv1w = (const float*)d_in[8];
    const float* conv1b = (const float*)d_in[9];
    const float* bng    = (const float*)d_in[10];
    const float* bnb    = (const float*)d_in[11];
    const float* capsw  = (const float*)d_in[12];
    const float* capsb  = (const float*)d_in[13];
    const float* routeW = (const float*)d_in[14];
    const float* routeb = (const float*)d_in[15];
    const float* fc1    = (const float*)d_in[16];
    const float* bn1g   = (const float*)d_in[17];
    const float* bn1b   = (const float*)d_in[18];
    const float* fc2    = (const float*)d_in[19];
    const float* bn2g   = (const float*)d_in[20];
    const float* bn2b   = (const float*)d_in[21];
    const float* fc3    = (const float*)d_in[22];
    float* out = (float*)d_out;

    cudaFuncSetAttribute(conv1_kernel,     cudaFuncAttributeMaxDynamicSharedMemorySize, CONV1_SMEM);
    cudaFuncSetAttribute(capsroute_kernel, cudaFuncAttributeMaxDynamicSharedMemorySize, CR_SMEM);
    cudaFuncSetAttribute(pl_kernel<3>, cudaFuncAttributeMaxDynamicSharedMemorySize, PL_SMEM);
    cudaFuncSetAttribute(pl_kernel<5>, cudaFuncAttributeMaxDynamicSharedMemorySize, PL_SMEM);
    cudaFuncSetAttribute(pl_kernel<7>, cudaFuncAttributeMaxDynamicSharedMemorySize, PL_SMEM);

    __half *h0, *h1, *w16;
    cudaGetSymbolAddress((void**)&h0,  g_h0);
    cudaGetSymbolAddress((void**)&h1,  g_h1);
    cudaGetSymbolAddress((void**)&w16, g_w16);

    prep_misc<<<42 + (BATCH * SEQ * 16 + 255) / 256, 256>>>(conv1w, capsw, x, emb);
    wprep_all<<<dim3(60, 41), 256>>>(W3, W5, W7);

    pl_kernel<3><<<dim3(32, 41), 512, PL_SMEM>>>(h0, w16 + WOFF3, b3, h1);
    pl_kernel<5><<<dim3(32, 41), 512, PL_SMEM>>>(h1, w16 + WOFF5, b5, h0);
    pl_kernel<7><<<dim3(32, 41), 512, PL_SMEM>>>(h0, w16 + WOFF7, b7, h1);

    conv1_kernel<<<BATCH / 2, 256, CONV1_SMEM>>>(conv1b);
    capsroute_kernel<<<BATCH, 256, CR_SMEM>>>(bng, bnb, capsb, routeW, routeb, fc1);
    head1_kernel<<<BATCH / 4, 256>>>(bn1g, bn1b, fc2);
    head2_kernel<<<(BATCH + 255) / 256, 256>>>(bn2g, bn2b, fc3, out);
}

// round 14
// speedup vs baseline: 1.0474x; 1.0474x over previous
#include <cuda_runtime.h>
#include <cuda_fp16.h>
#include <math.h>
#include <stdint.h>

// ---------------------------------------------------------------------------
// Problem constants
// ---------------------------------------------------------------------------
#define BATCH 4096
#define SEQ   41
#define FDIM  128
#define SF    (SEQ*FDIM)        // 5248
#define C64L  (64*128)          // 8192

// ---------------------------------------------------------------------------
// Scratch (device globals; allocation-free contract)
// ---------------------------------------------------------------------------
__device__ __align__(256) __half g_h0[(size_t)BATCH * SF];   // activation ping
__device__ __align__(256) __half g_h1[(size_t)BATCH * SF];   // activation pong
__device__ __align__(256) __half g_c[(size_t)BATCH * C64L];  // conv1 out [b][l=128][o=64]
__device__ __align__(256) float  g_g1[(size_t)BATCH * 128];  // [B,2,64]
__device__ __align__(256) float  g_g2[(size_t)BATCH * 64];   // [B,2,32]
__device__ double g_bnsum[64], g_bnsq[64];
__device__ double g_bn1acc[4];
__device__ double g_bn2acc[4];

// transposed fp16 PL weights: layout [s][n=128][K], layers packed
#define WOFF3 ((size_t)0)
#define WOFF5 ((size_t)41*384*128)
#define WOFF7 ((size_t)(41*384*128) + (size_t)41*640*128)
#define WTOT  ((size_t)41*1920*128)
__device__ __align__(256) __half g_w16[WTOT];

// conv weights fp16, pitched: wc1 [3][64][56], wc2 [3][64][40]
__device__ __align__(256) __half g_wc1[3*64*56];
__device__ __align__(256) __half g_wc2[3*64*40];

// single shared extern symbol for all dynamic-smem kernels
extern __shared__ __align__(1024) char sm_raw[];

__device__ __forceinline__ float squash_factor(float ssq) {
    float n = sqrtf(ssq);
    return (1.f - 1.f / (expf(n) + 1e-21f)) / (n + 1e-21f);
}

// ---------------------------------------------------------------------------
// PTX helpers (compute_100-safe: mma.sync + cp.async + ldmatrix)
// ---------------------------------------------------------------------------
__device__ __forceinline__ uint32_t smem_u32(const void* p) {
    uint32_t a;
    asm("{ .reg .u64 t; cvta.to.shared.u64 t, %1; cvt.u32.u64 %0, t; }" : "=r"(a) : "l"(p));
    return a;
}
__device__ __forceinline__ uint32_t lds32(uint32_t a) {
    uint32_t v;
    asm volatile("ld.shared.b32 %0, [%1];" : "=r"(v) : "r"(a));
    return v;
}
__device__ __forceinline__ void sts32(uint32_t a, uint32_t v) {
    asm volatile("st.shared.b32 [%0], %1;" :: "r"(a), "r"(v));
}
__device__ __forceinline__ void sts16(uint32_t a, uint16_t v) {
    asm volatile("st.shared.u16 [%0], %1;" :: "r"(a), "h"(v));
}
__device__ __forceinline__ void ldsm_x4(uint32_t* r, uint32_t addr) {
    asm volatile("ldmatrix.sync.aligned.m8n8.x4.shared.b16 {%0,%1,%2,%3}, [%4];"
        : "=r"(r[0]), "=r"(r[1]), "=r"(r[2]), "=r"(r[3]) : "r"(addr));
}
__device__ __forceinline__ void mma_f16(float* c, const uint32_t* a, const uint32_t* b) {
    asm volatile(
        "mma.sync.aligned.m16n8k16.row.col.f32.f16.f16.f32 "
        "{%0,%1,%2,%3}, {%4,%5,%6,%7}, {%8,%9}, {%0,%1,%2,%3};"
        : "+f"(c[0]), "+f"(c[1]), "+f"(c[2]), "+f"(c[3])
        : "r"(a[0]), "r"(a[1]), "r"(a[2]), "r"(a[3]), "r"(b[0]), "r"(b[1]));
}
#define CP16(dst, src)    asm volatile("cp.async.cg.shared.global [%0], [%1], 16;" :: "r"(dst), "l"(src))
#define CP_COMMIT()       asm volatile("cp.async.commit_group;" ::: "memory")
#define CP_WAIT0()        asm volatile("cp.async.wait_group 0;" ::: "memory")

__device__ __forceinline__ uint32_t hpack(float a, float b) {
    __half2 t = __floats2half2_rn(a, b);
    return *reinterpret_cast<uint32_t*>(&t);
}

// ---------------------------------------------------------------------------
// 0. prep_all (single launch):
//    blocks [0,2460): PL weight transpose (bx = blk%60, s = blk/60)
//    blocks [2460,2502): conv weight prep + accumulator zero
//    blocks [2502, ...): embedding gather
// ---------------------------------------------------------------------------
#define PREP_WBLK 2460
#define PREP_CBLK (PREP_WBLK + 42)
__global__ void prep_all(const float* __restrict__ W3, const float* __restrict__ W5,
                         const float* __restrict__ W7,
                         const float* __restrict__ c1w, const float* __restrict__ c2w,
                         const int* __restrict__ x, const float* __restrict__ emb) {
    __shared__ float tile[32][129];
    int blk = blockIdx.x, t = threadIdx.x;
    if (blk < PREP_WBLK) {
        int bx = blk % 60, s = blk / 60;
        const float* W; __half* o; int K, kb;
        if (bx < 12)      { W = W3; o = g_w16 + WOFF3; K = 384; kb = bx * 32; }
        else if (bx < 32) { W = W5; o = g_w16 + WOFF5; K = 640; kb = (bx - 12) * 32; }
        else              { W = W7; o = g_w16 + WOFF7; K = 896; kb = (bx - 32) * 32; }
#pragma unroll
        for (int i = 0; i < 16; i++) {
            int e = t + i * 256;
            int kk = e >> 7, n = e & 127;
            tile[kk][n] = W[((size_t)s * K + kb + kk) * 128 + n];
        }
        __syncthreads();
        int n = t >> 1, h = (t & 1) * 16;
        size_t ob = ((size_t)(s * 128 + n)) * K + kb + h;
#pragma unroll
        for (int kk = 0; kk < 16; kk += 2) {
            *reinterpret_cast<uint32_t*>(&o[ob + kk]) = hpack(tile[h + kk][n], tile[h + kk + 1][n]);
        }
    } else if (blk < PREP_CBLK) {
        int tt = (blk - PREP_WBLK) * 256 + t;
        if (blk == PREP_WBLK) {
            if (t < 64) { g_bnsum[t] = 0.0; g_bnsq[t] = 0.0; }
            if (t < 4)  { g_bn1acc[t] = 0.0; g_bn2acc[t] = 0.0; }
        }
        if (tt < 3 * 64 * 56) {
            int c = tt % 56, o = (tt / 56) % 64, k = tt / (56 * 64);
            g_wc1[tt] = (c < 41) ? __float2half(c1w[(o * 41 + c) * 3 + k]) : __float2half(0.f);
        }
        if (tt < 3 * 64 * 40) {
            int c = tt % 40, o = (tt / 40) % 64, k = tt / (40 * 64);
            g_wc2[tt] = (c < 32) ? __float2half(c2w[(o * 32 + c) * 3 + k]) : __float2half(0.f);
        }
    } else {
        int gid = (blk - PREP_CBLK) * 256 + t;
        int pos = gid >> 4;
        int f0  = (gid & 15) * 8;
        if (pos >= BATCH * SEQ) return;
        int e = x[pos];
        const float4* sp = reinterpret_cast<const float4*>(emb + e * FDIM + f0);
        float4 v0 = sp[0], v1 = sp[1];
        uint4 o;
        o.x = hpack(v0.x, v0.y); o.y = hpack(v0.z, v0.w);
        o.z = hpack(v1.x, v1.y); o.w = hpack(v1.z, v1.w);
        *reinterpret_cast<uint4*>(g_h0 + (size_t)pos * FDIM + f0) = o;
    }
}

// ---------------------------------------------------------------------------
// 2-4. position_linear: fp16 MMA, 256 threads, 8 warps 2(M)x4(N), warp tile
//      64x32 (duplication-optimal), K-chunk 64, ldmatrix, 3-stage pipeline.
// ---------------------------------------------------------------------------
#define PL_SMEM (3 * 32768)   // 98304

template<int WIN>
__global__ void __launch_bounds__(256, 2)
pl_kernel(const __half* __restrict__ aIn, const __half* __restrict__ wIn,
          const float* __restrict__ bst, __half* __restrict__ aOut)
{
    constexpr int P = WIN / 2;
    constexpr int K = WIN * 128;
    const uint32_t smb = smem_u32(sm_raw);
    const int s   = blockIdx.y;
    const int bm  = blockIdx.x * 128;
    const int tid = threadIdx.x;
    const int warp = tid >> 5, lane = tid & 31;
    const int warp_m = warp >> 2, warp_n = warp & 3;
    const int gid = lane >> 2, tg = lane & 3;

    const int j0 = (P - s) > 0 ? (P - s) : 0;
    const int j1 = (WIN - 1) < (P + SEQ - 1 - s) ? (WIN - 1) : (P + SEQ - 1 - s);
    const int nst = (j1 - j0 + 1) * 2;     // k64 stages (>= 4 always)

    const int a_moff = (lane & 7) + ((lane >> 3) & 1) * 8;
    const int a_cbit = lane >> 4;
    const int b_roff = ((lane >> 4) & 1) * 8 + (lane & 7);
    const int b_cbit = (lane >> 3) & 1;

    float acc[4][4][4];
#pragma unroll
    for (int a = 0; a < 4; a++)
#pragma unroll
        for (int b = 0; b < 4; b++)
#pragma unroll
            for (int c = 0; c < 4; c++) acc[a][b][c] = 0.f;

    auto load_stage = [&](int st) {
        const int jj = j0 + (st >> 1);
        const int f0 = (st & 1) * 64;
        const int tsrc = s + jj - P;
        const int k0 = jj * 128 + f0;
        const uint32_t sb = smb + (uint32_t)(st % 3) * 32768;
#pragma unroll
        for (int i = 0; i < 4; i++) {
            int idx = tid + i * 256;
            int row = idx >> 3, ch = idx & 7;
            uint32_t d = sb + row * 128 + (((ch ^ (row & 7)) << 4));
            size_t aoff = ((size_t)(bm + row) * SEQ + tsrc) * 128 + f0 + ch * 8;
            size_t boff = ((size_t)(s * 128 + row)) * K + k0 + ch * 8;
            CP16(d,         (const char*)(aIn + aoff));
            CP16(d + 16384, (const char*)(wIn + boff));
        }
        CP_COMMIT();
    };

    load_stage(0);
    load_stage(1);

    for (int st = 0; st < nst; st++) {
        if (st + 1 < nst) {
            asm volatile("cp.async.wait_group 1;" ::: "memory");
        } else {
            asm volatile("cp.async.wait_group 0;" ::: "memory");
        }
        __syncthreads();

        if (st + 2 < nst) load_stage(st + 2);

        const uint32_t ab = smb + (uint32_t)(st % 3) * 32768;
#pragma unroll
        for (int kt = 0; kt < 4; kt++) {
            uint32_t bf[4][2];
#pragma unroll
            for (int p = 0; p < 2; p++) {
                int row = warp_n * 32 + p * 16 + b_roff;
                int sw = row & 7;
                uint32_t addr = ab + 16384 + row * 128 + (((kt * 2 + b_cbit) ^ sw) << 4);
                uint32_t r[4];
                ldsm_x4(r, addr);
                bf[2 * p][0] = r[0]; bf[2 * p][1] = r[1];
                bf[2 * p + 1][0] = r[2]; bf[2 * p + 1][1] = r[3];
            }
#pragma unroll
            for (int mt = 0; mt < 4; mt++) {
                int row = warp_m * 64 + mt * 16 + a_moff;
                int sw = row & 7;
                uint32_t addr = ab + row * 128 + (((kt * 2 + a_cbit) ^ sw) << 4);
                uint32_t af[4];
                ldsm_x4(af, addr);
#pragma unroll
                for (int nt = 0; nt < 4; nt++)
                    mma_f16(acc[mt][nt], af, bf[nt]);
            }
        }
    }

    const float* bias = bst + s * 128;
#pragma unroll
    for (int mt = 0; mt < 4; mt++) {
        int rbase = warp_m * 64 + mt * 16 + gid;
#pragma unroll
        for (int half = 0; half < 2; half++) {
            int r = rbase + half * 8;
            size_t ob = ((size_t)(bm + r) * SEQ + s) * 128;
#pragma unroll
            for (int nt = 0; nt < 4; nt++) {
                int col = warp_n * 32 + nt * 8 + tg * 2;
                float v0 = fmaxf(acc[mt][nt][half * 2 + 0] + bias[col],     0.f);
                float v1 = fmaxf(acc[mt][nt][half * 2 + 1] + bias[col + 1], 0.f);
                *reinterpret_cast<uint32_t*>(aOut + ob + col) = hpack(v0, v1);
            }
        }
    }
}

// ---------------------------------------------------------------------------
// 5. conv1 via tensor cores. 2 batches per CTA, 3 CTAs/SM.
// ---------------------------------------------------------------------------
#define C1_STG   0
#define C1_A     10496
#define C1_W     (C1_A + 130*112)        // 25056
#define C1_STATS (C1_W + 3*64*112)       // 46560
#define CONV1_SMEM (C1_STATS + 2*64*4)   // 47072

__global__ void __launch_bounds__(256, 3)
conv1_kernel(const float* __restrict__ bias) {
    const uint32_t smb = smem_u32(sm_raw);
    const int t = threadIdx.x;
    const int warp = t >> 5, lane = t & 31;
    const int warp_m = warp >> 1, warp_n = warp & 1;
    const int gid = lane >> 2, tg = lane & 3;

    for (int i = t; i < 130 * 112 / 4; i += 256) sts32(smb + C1_A + i * 4, 0u);
    for (int i = t; i < 128; i += 256) sts32(smb + C1_STATS + i * 4, 0u);

    {
        const char* src = (const char*)(g_h1 + (size_t)(blockIdx.x * 2) * SF);
        for (int i = t; i < 41 * 16; i += 256)
            CP16(smb + C1_STG + i * 16, src + i * 16);
        const char* wsrc = (const char*)g_wc1;
        for (int i = t; i < 3 * 64 * 56 * 2 / 16; i += 256)
            CP16(smb + C1_W + i * 16, wsrc + i * 16);
        CP_COMMIT(); CP_WAIT0();
    }
    __syncthreads();

    float s0[4], s1[4], q0[4], q1[4];
#pragma unroll
    for (int nt = 0; nt < 4; nt++) { s0[nt] = s1[nt] = q0[nt] = q1[nt] = 0.f; }

    for (int bb2 = 0; bb2 < 2; bb2++) {
        const int b = blockIdx.x * 2 + bb2;

        for (int idx = t; idx < 41 * 64; idx += 256) {
            int c = idx >> 6, f2 = idx & 63;
            uint32_t v = lds32(smb + C1_STG + c * 256 + f2 * 4);
            sts16(smb + C1_A + (2 * f2 + 1) * 112 + c * 2, (uint16_t)(v & 0xFFFF));
            sts16(smb + C1_A + (2 * f2 + 2) * 112 + c * 2, (uint16_t)(v >> 16));
        }
        __syncthreads();

        if (bb2 == 0) {
            const char* src = (const char*)(g_h1 + (size_t)(b + 1) * SF);
            for (int i = t; i < 41 * 16; i += 256)
                CP16(smb + C1_STG + i * 16, src + i * 16);
            CP_COMMIT();
        }

        float acc[2][4][4];
#pragma unroll
        for (int a = 0; a < 2; a++)
#pragma unroll
            for (int bb = 0; bb < 4; bb++)
#pragma unroll
                for (int c = 0; c < 4; c++) acc[a][bb][c] = 0.f;

#pragma unroll
        for (int k = 0; k < 3; k++) {
#pragma unroll
            for (int ks = 0; ks < 3; ks++) {
                uint32_t bf[4][2];
#pragma unroll
                for (int nt = 0; nt < 4; nt++) {
                    uint32_t ba = smb + C1_W + k * (64 * 112) + (warp_n * 32 + nt * 8 + gid) * 112 + ks * 32 + tg * 4;
                    bf[nt][0] = lds32(ba);
                    bf[nt][1] = lds32(ba + 16);
                }
#pragma unroll
                for (int mt = 0; mt < 2; mt++) {
                    int r0 = warp_m * 32 + mt * 16 + gid + k;
                    uint32_t a0a = smb + C1_A + r0 * 112 + ks * 32 + tg * 4;
                    uint32_t a1a = a0a + 8 * 112;
                    uint32_t af[4];
                    af[0] = lds32(a0a);
                    af[1] = lds32(a1a);
                    af[2] = lds32(a0a + 16);
                    af[3] = lds32(a1a + 16);
#pragma unroll
                    for (int nt = 0; nt < 4; nt++)
                        mma_f16(acc[mt][nt], af, bf[nt]);
                }
            }
        }

        __half* dst = g_c + (size_t)b * C64L;
#pragma unroll
        for (int mt = 0; mt < 2; mt++) {
            int l0 = warp_m * 32 + mt * 16 + gid;
#pragma unroll
            for (int nt = 0; nt < 4; nt++) {
                int o = warp_n * 32 + nt * 8 + tg * 2;
                float bb0 = bias[o], bb1 = bias[o + 1];
                float v0 = acc[mt][nt][0] + bb0, v1 = acc[mt][nt][1] + bb1;
                float v2 = acc[mt][nt][2] + bb0, v3 = acc[mt][nt][3] + bb1;
                *reinterpret_cast<uint32_t*>(dst + l0 * 64 + o)       = hpack(v0, v1);
                *reinterpret_cast<uint32_t*>(dst + (l0 + 8) * 64 + o) = hpack(v2, v3);
                s0[nt] += v0 + v2; s1[nt] += v1 + v3;
                q0[nt] += v0 * v0 + v2 * v2; q1[nt] += v1 * v1 + v3 * v3;
            }
        }

        if (bb2 == 0) { CP_WAIT0(); }
        __syncthreads();
    }

#pragma unroll
    for (int nt = 0; nt < 4; nt++) {
#pragma unroll
        for (int off = 4; off < 32; off <<= 1) {
            s0[nt] += __shfl_xor_sync(0xffffffffu, s0[nt], off);
            s1[nt] += __shfl_xor_sync(0xffffffffu, s1[nt], off);
            q0[nt] += __shfl_xor_sync(0xffffffffu, q0[nt], off);
            q1[nt] += __shfl_xor_sync(0xffffffffu, q1[nt], off);
        }
    }
    if (gid == 0) {
        float* sums = reinterpret_cast<float*>(sm_raw + C1_STATS);
        float* sqs  = sums + 64;
#pragma unroll
        for (int nt = 0; nt < 4; nt++) {
            int o = warp_n * 32 + nt * 8 + tg * 2;
            atomicAdd(&sums[o],     s0[nt]);
            atomicAdd(&sums[o + 1], s1[nt]);
            atomicAdd(&sqs[o],      q0[nt]);
            atomicAdd(&sqs[o + 1],  q1[nt]);
        }
    }
    __syncthreads();
    if (t < 64) {
        float* sums = reinterpret_cast<float*>(sm_raw + C1_STATS);
        atomicAdd(&g_bnsum[t], (double)sums[t]);
        atomicAdd(&g_bnsq[t],  (double)sums[64 + t]);
    }
}

// ---------------------------------------------------------------------------
// 8-9. FUSED capsroute (3 CTAs/SM) — BN params computed locally
// ---------------------------------------------------------------------------
#define CR_A    0
#define CR_W    16640
#define CR_SOUT 32000
#define CR_SMEM (CR_SOUT + 128*73*4)   // 69376

__global__ void __launch_bounds__(256, 3)
capsroute_kernel(const float* __restrict__ bng, const float* __restrict__ bnb,
                 const float* __restrict__ cb,
                 const float* __restrict__ rW, const float* __restrict__ rb,
                 const float* __restrict__ fc1)
{
    const uint32_t smb = smem_u32(sm_raw);
    float* sout = reinterpret_cast<float*>(sm_raw + CR_SOUT);  // [128 l][73]
    __shared__ float bnsc[64], bnsh[64];
    __shared__ float red4[4][64];
    __shared__ float sfac[64];
    __shared__ float coef[2][64];
    __shared__ float warp_sq[8];
    __shared__ float factor_s[2];
    __shared__ float sv_s[2][128];
    __shared__ float yv_s[2][128];

    const int b = blockIdx.x, t = threadIdx.x;
    const int warp = t >> 5, lane = t & 31;
    const int warp_m = warp >> 1, g = warp & 1;
    const int gid = lane >> 2, tg = lane & 3;

    if (t < 64) {
        sts32(smb + CR_A + ((t < 32) ? 0 : (129 * 128)) + (t & 31) * 4, 0u);
        double inv = 1.0 / ((double)BATCH * 128.0);
        double mu = g_bnsum[t] * inv;
        double var = g_bnsq[t] * inv - mu * mu;
        float sc = bng[t] * rsqrtf((float)var + 1e-5f);
        bnsc[t] = sc;
        bnsh[t] = bnb[t] - (float)mu * sc;
    }

    {
        const char* src = (const char*)(g_c + (size_t)b * C64L);
        for (int i = t; i < 128 * 8; i += 256) {
            int row = (i >> 3) + 1, ch = i & 7;
            CP16(smb + CR_A + row * 128 + ((ch ^ (row & 7)) << 4), src + (row - 1) * 128 + ch * 16);
        }
        const char* wsrc = (const char*)g_wc2;
        for (int i = t; i < 3 * 64 * 40 * 2 / 16; i += 256)
            CP16(smb + CR_W + i * 16, wsrc + i * 16);
        CP_COMMIT(); CP_WAIT0();
    }
    __syncthreads();

    for (int idx = t; idx < 128 * 32; idx += 256) {
        int r = (idx >> 5) + 1, wd = idx & 31;
        int o = wd * 2;
        uint32_t addr = smb + CR_A + r * 128 + (((wd >> 2) ^ (r & 7)) << 4) + ((wd * 4) & 15);
        uint32_t v = lds32(addr);
        __half2 h = *reinterpret_cast<__half2*>(&v);
        float f0 = fmaxf(__low2float(h)  * bnsc[o]     + bnsh[o],     0.f);
        float f1 = fmaxf(__high2float(h) * bnsc[o + 1] + bnsh[o + 1], 0.f);
        sts32(addr, hpack(f0, f1));
    }
    __syncthreads();

    float acc[2][4][4];
#pragma unroll
    for (int a = 0; a < 2; a++)
#pragma unroll
        for (int bb = 0; bb < 4; bb++)
#pragma unroll
            for (int c = 0; c < 4; c++) acc[a][bb][c] = 0.f;

#pragma unroll
    for (int k = 0; k < 3; k++) {
#pragma unroll
        for (int ks = 0; ks < 2; ks++) {
            uint32_t bf[4][2];
#pragma unroll
            for (int nt = 0; nt < 4; nt++) {
                uint32_t ba = smb + CR_W + k * (64 * 80) + (g * 32 + nt * 8 + gid) * 80 + ks * 32 + tg * 4;
                bf[nt][0] = lds32(ba);
                bf[nt][1] = lds32(ba + 16);
            }
            int cbase = g * 4 + ks * 2;
#pragma unroll
            for (int mt = 0; mt < 2; mt++) {
                int r0 = warp_m * 32 + mt * 16 + gid + k;
                int r1 = r0 + 8;
                uint32_t af[4];
                af[0] = lds32(smb + CR_A + r0 * 128 + (((cbase)     ^ (r0 & 7)) << 4) + tg * 4);
                af[1] = lds32(smb + CR_A + r1 * 128 + (((cbase)     ^ (r1 & 7)) << 4) + tg * 4);
                af[2] = lds32(smb + CR_A + r0 * 128 + (((cbase + 1) ^ (r0 & 7)) << 4) + tg * 4);
                af[3] = lds32(smb + CR_A + r1 * 128 + (((cbase + 1) ^ (r1 & 7)) << 4) + tg * 4);
#pragma unroll
                for (int nt = 0; nt < 4; nt++)
                    mma_f16(acc[mt][nt], af, bf[nt]);
            }
        }
    }

#pragma unroll
    for (int mt = 0; mt < 2; mt++) {
        int l0 = warp_m * 32 + mt * 16 + gid;
#pragma unroll
        for (int nt = 0; nt < 4; nt++) {
            int o = g * 32 + nt * 8 + tg * 2;
            float bb0 = cb[o], bb1 = cb[o + 1];
            sout[l0 * 73 + o]           = acc[mt][nt][0] + bb0;
            sout[l0 * 73 + o + 1]       = acc[mt][nt][1] + bb1;
            sout[(l0 + 8) * 73 + o]     = acc[mt][nt][2] + bb0;
            sout[(l0 + 8) * 73 + o + 1] = acc[mt][nt][3] + bb1;
        }
    }
    __syncthreads();

    {
        int o = t & 63, seg = t >> 6;
        float p = 0.f;
        for (int l = seg * 32; l < seg * 32 + 32; l++) {
            float v = sout[l * 73 + o];
            p += v * v;
        }
        red4[seg][o] = p;
    }
    __syncthreads();
    if (t < 64) {
        float tot = red4[0][t] + red4[1][t] + red4[2][t] + red4[3][t];
        sfac[t] = squash_factor(tot);
    }
    __syncthreads();
    if (t < 128) {
        int i = t >> 6, j = t & 63;
        coef[i][j] = sfac[j] * (1.0f + rb[i * 64 + j]);
    }
    __syncthreads();

    int i = t >> 7;
    int f = t & 127;
    float acc2 = 0.f;
    const float* rwi = rW + i * 8192 + f;
    const float* srow = sout + f * 73;
#pragma unroll 8
    for (int j = 0; j < 64; j++)
        acc2 += srow[j] * rwi[j * 128] * coef[i][j];

    float sq = acc2 * acc2;
    for (int off = 16; off; off >>= 1) sq += __shfl_xor_sync(0xffffffffu, sq, off);
    if ((t & 31) == 0) warp_sq[t >> 5] = sq;
    __syncthreads();
    if (t < 2) {
        float tot = warp_sq[t * 4 + 0] + warp_sq[t * 4 + 1] + warp_sq[t * 4 + 2] + warp_sq[t * 4 + 3];
        factor_s[t] = squash_factor(tot);
    }
    __syncthreads();
    sv_s[i][f] = acc2 * factor_s[i];
    __syncthreads();
    yv_s[i][f] = sv_s[i][f] + fmaxf(sv_s[0][f], sv_s[1][f]);
    __syncthreads();

    {
        int ii = t >> 7;
        int o  = (t >> 1) & 63;
        int p  = t & 1;
        float a = 0.f;
        const float* yb = yv_s[ii];
        const float* fb = fc1 + p * 64 * 64 + o;
#pragma unroll 8
        for (int ff = 0; ff < 64; ff++) a += yb[p * 64 + ff] * fb[ff * 64];
        a += __shfl_xor_sync(0xffffffffu, a, 1);
        double s = 0.0, q = 0.0;
        if (p == 0) {
            g_g1[(size_t)b * 128 + ii * 64 + o] = a;
            s = a; q = (double)a * a;
        }
        for (int off = 16; off; off >>= 1) {
            s += __shfl_xor_sync(0xffffffffu, s, off);
            q += __shfl_xor_sync(0xffffffffu, q, off);
        }
        if ((t & 31) == 0) {
            atomicAdd(&g_bn1acc[ii], s);
            atomicAdd(&g_bn1acc[2 + ii], q);
        }
    }
}

// ---------------------------------------------------------------------------
// 11. head1 (bn1 params computed locally)
// ---------------------------------------------------------------------------
__global__ void head1_kernel(const float* __restrict__ bn1g, const float* __restrict__ bn1b,
                             const float* __restrict__ fc2) {
    __shared__ float a_s[4][128];
    __shared__ float p1[4];
    int t = threadIdx.x;
    if (t < 2) {
        double inv = 1.0 / ((double)BATCH * 64.0);
        double mu = g_bn1acc[t] * inv;
        double var = g_bn1acc[2 + t] * inv - mu * mu;
        float sc = bn1g[t] * rsqrtf((float)var + 1e-5f);
        p1[t] = sc;
        p1[2 + t] = bn1b[t] - (float)mu * sc;
    }
    __syncthreads();
    for (int idx = t; idx < 512; idx += 256) {
        int lbb = idx >> 7, rr = idx & 127;
        int ii = rr >> 6;
        float v = g_g1[(size_t)(blockIdx.x * 4 + lbb) * 128 + rr];
        a_s[lbb][rr] = fmaxf(v * p1[ii] + p1[2 + ii], 0.f);
    }
    __syncthreads();
    int lb = t >> 6, r = t & 63;
    int b = blockIdx.x * 4 + lb;
    int ii = r >> 5, m = r & 31;
    float acc = 0.f;
    const float* arow = &a_s[lb][ii * 64];
#pragma unroll 8
    for (int o = 0; o < 64; o++) acc += arow[o] * fc2[o * 32 + m];
    g_g2[(size_t)b * 64 + ii * 32 + m] = acc;
    double s = acc, q = (double)acc * acc;
    for (int off = 16; off; off >>= 1) {
        s += __shfl_xor_sync(0xffffffffu, s, off);
        q += __shfl_xor_sync(0xffffffffu, q, off);
    }
    if ((t & 31) == 0) {
        atomicAdd(&g_bn2acc[ii], s);
        atomicAdd(&g_bn2acc[2 + ii], q);
    }
}

// ---------------------------------------------------------------------------
// 13. head2 (bn2 params computed locally)
// ---------------------------------------------------------------------------
__global__ void head2_kernel(const float* __restrict__ bn2g, const float* __restrict__ bn2b,
                             const float* __restrict__ fc3, float* __restrict__ out) {
    __shared__ float p2[4];
    if (threadIdx.x < 2) {
        int i = threadIdx.x;
        double inv = 1.0 / ((double)BATCH * 32.0);
        double mu = g_bn2acc[i] * inv;
        double var = g_bn2acc[2 + i] * inv - mu * mu;
        float sc = bn2g[i] * rsqrtf((float)var + 1e-5f);
        p2[i] = sc;
        p2[2 + i] = bn2b[i] - (float)mu * sc;
    }
    __syncthreads();
    int b = blockIdx.x * 256 + threadIdx.x;
    if (b >= BATCH) return;
    float best = -1e30f;
#pragma unroll
    for (int i = 0; i < 2; i++) {
        float sc = p2[i], sh = p2[2 + i];
        float s = 0.f;
#pragma unroll
        for (int m = 0; m < 32; m++) {
            float v = fmaxf(g_g2[(size_t)b * 64 + i * 32 + m] * sc + sh, 0.f);
            s += v * fc3[m];
        }
        float sig = 1.f / (1.f + expf(-s));
        best = fmaxf(best, sig);
    }
    out[b] = best;
}

// ---------------------------------------------------------------------------
// launch
// ---------------------------------------------------------------------------
extern "C" void kernel_launch(void* const* d_in, const int* in_sizes, int n_in,
                              void* d_out, int out_size)
{
    const int*   x      = (const int*)d_in[0];
    const float* emb    = (const float*)d_in[1];
    const float* W3     = (const float*)d_in[2];
    const float* b3     = (const float*)d_in[3];
    const float* W5     = (const float*)d_in[4];
    const float* b5     = (const float*)d_in[5];
    const float* W7     = (const float*)d_in[6];
    const float* b7     = (const float*)d_in[7];
    const float* conv1w = (const float*)d_in[8];
    const float* conv1b = (const float*)d_in[9];
    const float* bng    = (const float*)d_in[10];
    const float* bnb    = (const float*)d_in[11];
    const float* capsw  = (const float*)d_in[12];
    const float* capsb  = (const float*)d_in[13];
    const float* routeW = (const float*)d_in[14];
    const float* routeb = (const float*)d_in[15];
    const float* fc1    = (const float*)d_in[16];
    const float* bn1g   = (const float*)d_in[17];
    const float* bn1b   = (const float*)d_in[18];
    const float* fc2    = (const float*)d_in[19];
    const float* bn2g   = (const float*)d_in[20];
    const float* bn2b   = (const float*)d_in[21];
    const float* fc3    = (const float*)d_in[22];
    float* out = (float*)d_out;

    cudaFuncSetAttribute(conv1_kernel,     cudaFuncAttributeMaxDynamicSharedMemorySize, CONV1_SMEM);
    cudaFuncSetAttribute(capsroute_kernel, cudaFuncAttributeMaxDynamicSharedMemorySize, CR_SMEM);
    cudaFuncSetAttribute(pl_kernel<3>, cudaFuncAttributeMaxDynamicSharedMemorySize, PL_SMEM);
    cudaFuncSetAttribute(pl_kernel<5>, cudaFuncAttributeMaxDynamicSharedMemorySize, PL_SMEM);
    cudaFuncSetAttribute(pl_kernel<7>, cudaFuncAttributeMaxDynamicSharedMemorySize, PL_SMEM);

    __half *h0, *h1, *w16;
    cudaGetSymbolAddress((void**)&h0,  g_h0);
    cudaGetSymbolAddress((void**)&h1,  g_h1);
    cudaGetSymbolAddress((void**)&w16, g_w16);

    prep_all<<<PREP_CBLK + (BATCH * SEQ * 16 + 255) / 256, 256>>>(W3, W5, W7, conv1w, capsw, x, emb);

    pl_kernel<3><<<dim3(32, 41), 256, PL_SMEM>>>(h0, w16 + WOFF3, b3, h1);
    pl_kernel<5><<<dim3(32, 41), 256, PL_SMEM>>>(h1, w16 + WOFF5, b5, h0);
    pl_kernel<7><<<dim3(32, 41), 256, PL_SMEM>>>(h0, w16 + WOFF7, b7, h1);

    conv1_kernel<<<BATCH / 2, 256, CONV1_SMEM>>>(conv1b);
    capsroute_kernel<<<BATCH, 256, CR_SMEM>>>(bng, bnb, capsb, routeW, routeb, fc1);
    head1_kernel<<<BATCH / 4, 256>>>(bn1g, bn1b, fc2);
    head2_kernel<<<(BATCH + 255) / 256, 256>>>(bn2g, bn2b, fc3, out);
}